// round 11
// baseline (speedup 1.0000x reference)
#include <cuda_runtime.h>
#include <cuda_fp16.h>

#define MAX_EDGES 3200000
#define MAX_NODES 100000
#define EPS 1e-8f

#define GRID_B 148                 // <= #SMs: every block resident in wave 1
#define TPB 512
#define TEAMS_PER_BLOCK (TPB / 2)  // 256
#define TOTAL_TEAMS (GRID_B * TEAMS_PER_BLOCK)  // 37888

// Scratch (device globals -- no allocation allowed)
__device__ float g_rowsum[MAX_NODES];
__device__ __align__(16) __half g_emb1h[MAX_NODES * 16];
__device__ __align__(16) __half g_emb2h[MAX_NODES * 16];

// Software grid barrier state (self-resetting; replay-safe)
__device__ unsigned g_bar_count = 0;
__device__ volatile unsigned g_bar_gen = 0;

__device__ __forceinline__ void grid_barrier() {
    __syncthreads();
    __threadfence();
    if (threadIdx.x == 0) {
        unsigned my = g_bar_gen;
        if (atomicAdd(&g_bar_count, 1u) == GRID_B - 1u) {
            atomicExch(&g_bar_count, 0u);
            __threadfence();
            g_bar_gen = my + 1u;
        } else {
            while (g_bar_gen == my) { __nanosleep(64); }
        }
    }
    __syncthreads();
    __threadfence();
}

__device__ __forceinline__ float dot8h(uint4 a, uint4 b) {
    const __half2* ah = (const __half2*)&a;
    const __half2* bh = (const __half2*)&b;
    float acc = 0.0f;
#pragma unroll
    for (int k = 0; k < 4; k++) {
        float2 fa = __half22float2(ah[k]);
        float2 fb = __half22float2(bh[k]);
        acc = fmaf(fa.x, fb.x, acc);
        acc = fmaf(fa.y, fb.y, acc);
    }
    return acc;
}

__global__ void __launch_bounds__(TPB, 1)
fused_kernel(const int* __restrict__ src,
             const int* __restrict__ dst,
             const float4* __restrict__ emb1,
             const float4* __restrict__ emb2,
             float* __restrict__ out,
             int n_edges, int n_nodes, int ept) {
    extern __shared__ float s_w[];  // TEAMS_PER_BLOCK * ept floats

    int tid_g = blockIdx.x * TPB + threadIdx.x;

    // ---------------- Phase A: fp16 table conversion + rowsum zero ----------
    {
        int total = 3 * n_nodes;
        for (int i = tid_g; i < total; i += GRID_B * TPB) {
            if (i < 2 * n_nodes) {
                bool first = (i < n_nodes);
                int row = first ? i : i - n_nodes;
                const float4* sp = (first ? emb1 : emb2) + (size_t)row * 4;
                __half* dp = (first ? g_emb1h : g_emb2h) + (size_t)row * 16;
                float4 v0 = __ldg(sp + 0);
                float4 v1 = __ldg(sp + 1);
                float4 v2 = __ldg(sp + 2);
                float4 v3 = __ldg(sp + 3);
                __half2 h0 = __floats2half2_rn(v0.x, v0.y);
                __half2 h1 = __floats2half2_rn(v0.z, v0.w);
                __half2 h2 = __floats2half2_rn(v1.x, v1.y);
                __half2 h3 = __floats2half2_rn(v1.z, v1.w);
                __half2 h4 = __floats2half2_rn(v2.x, v2.y);
                __half2 h5 = __floats2half2_rn(v2.z, v2.w);
                __half2 h6 = __floats2half2_rn(v3.x, v3.y);
                __half2 h7 = __floats2half2_rn(v3.z, v3.w);
                uint4 lo = make_uint4(*(unsigned*)&h0, *(unsigned*)&h1,
                                      *(unsigned*)&h2, *(unsigned*)&h3);
                uint4 hi = make_uint4(*(unsigned*)&h4, *(unsigned*)&h5,
                                      *(unsigned*)&h6, *(unsigned*)&h7);
                ((uint4*)dp)[0] = lo;
                ((uint4*)dp)[1] = hi;
            } else {
                g_rowsum[i - 2 * n_nodes] = 0.0f;
            }
        }
    }

    grid_barrier();

    // ---------------- Phase B: edge scores -> smem w, rowsum REDG ----------
    int block_begin = blockIdx.x * TEAMS_PER_BLOCK * ept;
    {
        int team_in_blk = threadIdx.x >> 1;
        int half_sel = threadIdx.x & 1;
        // Pair mask: ONLY the two cooperating lanes. Pairs have identical trip
        // counts, so convergence within the mask is guaranteed even when teams
        // in the same warp have different (clamped) ranges. Full-warp masks
        // here deadlock on divergent trip counts (root cause of R6/R7 hangs).
        unsigned lane = threadIdx.x & 31u;
        unsigned pair_mask = 3u << (lane & ~1u);

        int e_begin = block_begin + team_in_blk * ept;  // multiple of 4
        int e_end = e_begin + ept;
        if (e_begin > n_edges) e_begin = n_edges;
        if (e_end > n_edges) e_end = n_edges;

        int e0 = e_begin;
        // 4-edge main loop: 8 independent 16B gathers per lane in flight
        for (; e0 + 3 < e_end; e0 += 4) {
            int4 s4 = *(const int4*)(src + e0);  // e0 % 4 == 0 -> 16B aligned
            int4 d4 = *(const int4*)(dst + e0);

            uint4 av0 = __ldg((const uint4*)(g_emb1h + (size_t)s4.x * 16) + half_sel);
            uint4 bv0 = __ldg((const uint4*)(g_emb2h + (size_t)d4.x * 16) + half_sel);
            uint4 av1 = __ldg((const uint4*)(g_emb1h + (size_t)s4.y * 16) + half_sel);
            uint4 bv1 = __ldg((const uint4*)(g_emb2h + (size_t)d4.y * 16) + half_sel);
            uint4 av2 = __ldg((const uint4*)(g_emb1h + (size_t)s4.z * 16) + half_sel);
            uint4 bv2 = __ldg((const uint4*)(g_emb2h + (size_t)d4.z * 16) + half_sel);
            uint4 av3 = __ldg((const uint4*)(g_emb1h + (size_t)s4.w * 16) + half_sel);
            uint4 bv3 = __ldg((const uint4*)(g_emb2h + (size_t)d4.w * 16) + half_sel);

            float a0 = dot8h(av0, bv0);
            float a1 = dot8h(av1, bv1);
            float a2 = dot8h(av2, bv2);
            float a3 = dot8h(av3, bv3);
            a0 += __shfl_xor_sync(pair_mask, a0, 1);
            a1 += __shfl_xor_sync(pair_mask, a1, 1);
            a2 += __shfl_xor_sync(pair_mask, a2, 1);
            a3 += __shfl_xor_sync(pair_mask, a3, 1);

            if (half_sel == 0) {
                int k = e0 - block_begin;
                float w0 = __frcp_rn(1.0f + __expf(-a0));
                float w1 = __frcp_rn(1.0f + __expf(-a1));
                float w2 = __frcp_rn(1.0f + __expf(-a2));
                float w3 = __frcp_rn(1.0f + __expf(-a3));
                s_w[k + 0] = w0;
                s_w[k + 1] = w1;
                s_w[k + 2] = w2;
                s_w[k + 3] = w3;
                atomicAdd(&g_rowsum[s4.x], w0);
                atomicAdd(&g_rowsum[s4.y], w1);
                atomicAdd(&g_rowsum[s4.z], w2);
                atomicAdd(&g_rowsum[s4.w], w3);
            }
        }
        // tail (1-3 edges)
        for (; e0 < e_end; e0++) {
            int s = src[e0];
            int d = dst[e0];
            uint4 av = __ldg((const uint4*)(g_emb1h + (size_t)s * 16) + half_sel);
            uint4 bv = __ldg((const uint4*)(g_emb2h + (size_t)d * 16) + half_sel);
            float a = dot8h(av, bv);
            a += __shfl_xor_sync(pair_mask, a, 1);
            if (half_sel == 0) {
                float w = __frcp_rn(1.0f + __expf(-a));
                s_w[e0 - block_begin] = w;
                atomicAdd(&g_rowsum[s], w);
            }
        }
    }

    grid_barrier();

    // ---------------- Phase C: normalize from smem w + rowsum gather -------
    {
        int n_local = TEAMS_PER_BLOCK * ept;
        if (block_begin >= n_edges) n_local = 0;
        else if (block_begin + n_local > n_edges) n_local = n_edges - block_begin;
#pragma unroll 4
        for (int k = threadIdx.x; k < n_local; k += TPB) {
            int s = __ldg(src + block_begin + k);
            float rs = g_rowsum[s];
            out[block_begin + k] = s_w[k] * __frcp_rn(rs + EPS);
        }
    }
}

extern "C" void kernel_launch(void* const* d_in, const int* in_sizes, int n_in,
                              void* d_out, int out_size) {
    const int*    src  = (const int*)d_in[0];
    const int*    dst  = (const int*)d_in[1];
    const float4* emb1 = (const float4*)d_in[2];
    const float4* emb2 = (const float4*)d_in[3];
    float*        out  = (float*)d_out;

    int n_edges = in_sizes[0];
    int n_nodes = in_sizes[2] / 16;

    // edges per team: multiple of 4, covers all edges
    int ept = (n_edges + TOTAL_TEAMS - 1) / TOTAL_TEAMS;
    ept = (ept + 3) & ~3;
    if (ept < 4) ept = 4;

    size_t smem_bytes = (size_t)TEAMS_PER_BLOCK * ept * sizeof(float);
    cudaFuncSetAttribute(fused_kernel,
                         cudaFuncAttributeMaxDynamicSharedMemorySize,
                         (int)smem_bytes);

    fused_kernel<<<GRID_B, TPB, smem_bytes>>>(src, dst, emb1, emb2, out,
                                              n_edges, n_nodes, ept);
}

// round 12
// speedup vs baseline: 1.4148x; 1.4148x over previous
#include <cuda_runtime.h>
#include <cuda_fp16.h>

#define MAX_EDGES 3200000
#define MAX_NODES 100000
#define EPS 1e-8f

// Scratch (device globals -- no allocation allowed)
__device__ float g_w[MAX_EDGES];
__device__ float g_rowsum[MAX_NODES];
__device__ __align__(16) __half g_emb1h[MAX_NODES * 16];
__device__ __align__(16) __half g_emb2h[MAX_NODES * 16];

// Prep: one thread per embedding ROW (64B in -> 32B out), plus rowsum zeroing.
__global__ void prep_kernel(const float4* __restrict__ emb1,
                            const float4* __restrict__ emb2,
                            int n_nodes) {
    int i = blockIdx.x * blockDim.x + threadIdx.x;
    if (i < 2 * n_nodes) {
        bool first = (i < n_nodes);
        int row = first ? i : i - n_nodes;
        const float4* srcp = (first ? emb1 : emb2) + (size_t)row * 4;
        __half* dstp = (first ? g_emb1h : g_emb2h) + (size_t)row * 16;
        float4 v0 = __ldg(srcp + 0);
        float4 v1 = __ldg(srcp + 1);
        float4 v2 = __ldg(srcp + 2);
        float4 v3 = __ldg(srcp + 3);
        __half2 h0 = __floats2half2_rn(v0.x, v0.y);
        __half2 h1 = __floats2half2_rn(v0.z, v0.w);
        __half2 h2 = __floats2half2_rn(v1.x, v1.y);
        __half2 h3 = __floats2half2_rn(v1.z, v1.w);
        __half2 h4 = __floats2half2_rn(v2.x, v2.y);
        __half2 h5 = __floats2half2_rn(v2.z, v2.w);
        __half2 h6 = __floats2half2_rn(v3.x, v3.y);
        __half2 h7 = __floats2half2_rn(v3.z, v3.w);
        uint4 lo = make_uint4(*(unsigned*)&h0, *(unsigned*)&h1,
                              *(unsigned*)&h2, *(unsigned*)&h3);
        uint4 hi = make_uint4(*(unsigned*)&h4, *(unsigned*)&h5,
                              *(unsigned*)&h6, *(unsigned*)&h7);
        ((uint4*)dstp)[0] = lo;
        ((uint4*)dstp)[1] = hi;
    } else if (i < 3 * n_nodes) {
        g_rowsum[i - 2 * n_nodes] = 0.0f;
    }
}

__device__ __forceinline__ float dot8h(uint4 a, uint4 b) {
    const __half2* ah = (const __half2*)&a;
    const __half2* bh = (const __half2*)&b;
    float acc = 0.0f;
#pragma unroll
    for (int k = 0; k < 4; k++) {
        float2 fa = __half22float2(ah[k]);
        float2 fb = __half22float2(bh[k]);
        acc = fmaf(fa.x, fb.x, acc);
        acc = fmaf(fa.y, fb.y, acc);
    }
    return acc;
}

// Pass 1 (R2-exact shape): 2 lanes per edge; each lane loads one 16B half of
// both 32B fp16 rows, partial dot, pair shfl reduce; even lane does
// sigmoid + store + rowsum atomic.
__global__ void edge_score_kernel(const int* __restrict__ src,
                                  const int* __restrict__ dst,
                                  int n_edges) {
    int tid = blockIdx.x * blockDim.x + threadIdx.x;
    int e = tid >> 1;
    int half_sel = tid & 1;
    if (e >= n_edges) return;

    int s = src[e];
    int d = dst[e];

    uint4 av = *((const uint4*)(g_emb1h + (size_t)s * 16) + half_sel);
    uint4 bv = *((const uint4*)(g_emb2h + (size_t)d * 16) + half_sel);

    float acc = dot8h(av, bv);
    acc += __shfl_xor_sync(0xffffffffu, acc, 1);

    if (half_sel == 0) {
        float w = __frcp_rn(1.0f + __expf(-acc));
        g_w[e] = w;
        atomicAdd(&g_rowsum[s], w);
    }
}

// Pass 2 (R2-exact shape): normalize, 4 edges per thread.
__global__ void normalize_kernel(const int4* __restrict__ src4,
                                 float4* __restrict__ out4,
                                 int n_quads) {
    int i = blockIdx.x * blockDim.x + threadIdx.x;
    if (i >= n_quads) return;
    int4 s = src4[i];
    float4 w = ((const float4*)g_w)[i];
    float4 o;
    o.x = w.x / (g_rowsum[s.x] + EPS);
    o.y = w.y / (g_rowsum[s.y] + EPS);
    o.z = w.z / (g_rowsum[s.z] + EPS);
    o.w = w.w / (g_rowsum[s.w] + EPS);
    out4[i] = o;
}

// Tail (n_edges not divisible by 4)
__global__ void normalize_tail_kernel(const int* __restrict__ src,
                                      float* __restrict__ out,
                                      int start, int n_edges) {
    int e = start + blockIdx.x * blockDim.x + threadIdx.x;
    if (e >= n_edges) return;
    out[e] = g_w[e] / (g_rowsum[src[e]] + EPS);
}

extern "C" void kernel_launch(void* const* d_in, const int* in_sizes, int n_in,
                              void* d_out, int out_size) {
    const int*    src  = (const int*)d_in[0];
    const int*    dst  = (const int*)d_in[1];
    const float4* emb1 = (const float4*)d_in[2];
    const float4* emb2 = (const float4*)d_in[3];
    float*        out  = (float*)d_out;

    int n_edges = in_sizes[0];
    int n_nodes = in_sizes[2] / 16;

    const int T = 256;

    int prep_items = 3 * n_nodes;
    prep_kernel<<<(prep_items + T - 1) / T, T>>>(emb1, emb2, n_nodes);

    int score_threads = 2 * n_edges;
    edge_score_kernel<<<(score_threads + T - 1) / T, T>>>(src, dst, n_edges);

    int n_quads = n_edges / 4;
    if (n_quads > 0)
        normalize_kernel<<<(n_quads + T - 1) / T, T>>>((const int4*)src,
                                                       (float4*)out, n_quads);
    int tail_start = n_quads * 4;
    int tail = n_edges - tail_start;
    if (tail > 0)
        normalize_tail_kernel<<<1, 64>>>(src, out, tail_start, n_edges);
}

// round 13
// speedup vs baseline: 1.4576x; 1.0303x over previous
#include <cuda_runtime.h>
#include <cuda_fp16.h>

#define MAX_EDGES 3200000
#define MAX_NODES 100000
#define EPS 1e-8f

// Scratch (device globals -- no allocation allowed)
__device__ float g_w[MAX_EDGES];
__device__ float g_rowsum[MAX_NODES];
__device__ __align__(16) __half g_emb1h[MAX_NODES * 16];
__device__ __align__(16) __half g_emb2h[MAX_NODES * 16];

// Prep (R2 shape, exact grid, straight-line): one thread per float4.
//   i in [0, n4):        convert emb1 float4 i  -> 8B fp16 store
//   i in [n4, 2*n4):     convert emb2 float4 i-n4
//   i in [2*n4, +nodes): zero rowsum
__global__ void prep_kernel(const float4* __restrict__ emb1,
                            const float4* __restrict__ emb2,
                            int n_nodes) {
    int n4 = n_nodes * 4;
    int i = blockIdx.x * blockDim.x + threadIdx.x;
    if (i < 2 * n4) {
        float4 v = (i < n4) ? __ldg(emb1 + i) : __ldg(emb2 + (i - n4));
        __half2 h0 = __floats2half2_rn(v.x, v.y);
        __half2 h1 = __floats2half2_rn(v.z, v.w);
        uint2 u = make_uint2(*(unsigned*)&h0, *(unsigned*)&h1);
        if (i < n4) ((uint2*)g_emb1h)[i] = u;
        else        ((uint2*)g_emb2h)[i - n4] = u;
    } else if (i < 2 * n4 + n_nodes) {
        g_rowsum[i - 2 * n4] = 0.0f;
    }
}

__device__ __forceinline__ float dot8h(uint4 a, uint4 b) {
    const __half2* ah = (const __half2*)&a;
    const __half2* bh = (const __half2*)&b;
    float acc = 0.0f;
#pragma unroll
    for (int k = 0; k < 4; k++) {
        float2 fa = __half22float2(ah[k]);
        float2 fb = __half22float2(bh[k]);
        acc = fmaf(fa.x, fb.x, acc);
        acc = fmaf(fa.y, fb.y, acc);
    }
    return acc;
}

// Pass 1: 2 lanes per edge; each lane loads one 16B half of both 32B fp16
// rows (pair lanes coalesce to one 128B-line wavefront per row), pair shfl
// reduce; even lane does sigmoid + store + rowsum REDG.
__global__ void edge_score_kernel(const int* __restrict__ src,
                                  const int* __restrict__ dst,
                                  int n_edges) {
    int tid = blockIdx.x * blockDim.x + threadIdx.x;
    int e = tid >> 1;
    int half_sel = tid & 1;
    if (e >= n_edges) return;

    int s = src[e];
    int d = dst[e];

    uint4 av = *((const uint4*)(g_emb1h + (size_t)s * 16) + half_sel);
    uint4 bv = *((const uint4*)(g_emb2h + (size_t)d * 16) + half_sel);

    float acc = dot8h(av, bv);
    acc += __shfl_xor_sync(0xffffffffu, acc, 1);

    if (half_sel == 0) {
        float w = __frcp_rn(1.0f + __expf(-acc));
        g_w[e] = w;
        atomicAdd(&g_rowsum[s], w);
    }
}

// Pass 2: normalize, 4 edges per thread.
__global__ void normalize_kernel(const int4* __restrict__ src4,
                                 float4* __restrict__ out4,
                                 int n_quads) {
    int i = blockIdx.x * blockDim.x + threadIdx.x;
    if (i >= n_quads) return;
    int4 s = src4[i];
    float4 w = ((const float4*)g_w)[i];
    float4 o;
    o.x = w.x / (g_rowsum[s.x] + EPS);
    o.y = w.y / (g_rowsum[s.y] + EPS);
    o.z = w.z / (g_rowsum[s.z] + EPS);
    o.w = w.w / (g_rowsum[s.w] + EPS);
    out4[i] = o;
}

// Tail (n_edges not divisible by 4)
__global__ void normalize_tail_kernel(const int* __restrict__ src,
                                      float* __restrict__ out,
                                      int start, int n_edges) {
    int e = start + blockIdx.x * blockDim.x + threadIdx.x;
    if (e >= n_edges) return;
    out[e] = g_w[e] / (g_rowsum[src[e]] + EPS);
}

extern "C" void kernel_launch(void* const* d_in, const int* in_sizes, int n_in,
                              void* d_out, int out_size) {
    const int*    src  = (const int*)d_in[0];
    const int*    dst  = (const int*)d_in[1];
    const float4* emb1 = (const float4*)d_in[2];
    const float4* emb2 = (const float4*)d_in[3];
    float*        out  = (float*)d_out;

    int n_edges = in_sizes[0];
    int n_nodes = in_sizes[2] / 16;

    const int T = 256;

    int prep_items = 8 * n_nodes + n_nodes;  // 2*n4 + n_nodes
    prep_kernel<<<(prep_items + T - 1) / T, T>>>(emb1, emb2, n_nodes);

    int score_threads = 2 * n_edges;
    edge_score_kernel<<<(score_threads + T - 1) / T, T>>>(src, dst, n_edges);

    int n_quads = n_edges / 4;
    if (n_quads > 0)
        normalize_kernel<<<(n_quads + T - 1) / T, T>>>((const int4*)src,
                                                       (float4*)out, n_quads);
    int tail_start = n_quads * 4;
    int tail = n_edges - tail_start;
    if (tail > 0)
        normalize_tail_kernel<<<1, 64>>>(src, out, tail_start, n_edges);
}